// round 15
// baseline (speedup 1.0000x reference)
#include <cuda_runtime.h>
#include <cuda_fp16.h>
#include <cstdint>
#include <math.h>

#define B_   2
#define S_   2048
#define HID_ 2048
#define NH_  16
#define HD_  128
#define KDIM 2048
#define BNHS (B_ * NH_ * S_)

typedef __half h16;

// ---- persistent buffers ----
__device__ float g_qkv[(size_t)3 * BNHS * HD_];   // [which][b][h][s][d] fp32
__device__ h16 g_xh[(size_t)B_ * S_ * HID_];
__device__ h16 g_xl[(size_t)B_ * S_ * HID_];
__device__ h16 g_wqf[(size_t)3 * HID_ * HID_];
__device__ h16 g_wof[(size_t)HID_ * HID_];
__device__ h16 g_qh[(size_t)BNHS * HD_];
__device__ h16 g_ql[(size_t)BNHS * HD_];
__device__ h16 g_kf[(size_t)BNHS * HD_];
__device__ h16 g_vf[(size_t)BNHS * HD_];
__device__ h16 g_ctxh[(size_t)B_ * S_ * HID_];    // [b][s][h][d]
__device__ h16 g_ctxl[(size_t)B_ * S_ * HID_];

// ---------------- helpers ----------------
__device__ __forceinline__ uint32_t s2u(const void* p) {
    return (uint32_t)__cvta_generic_to_shared(p);
}
__device__ __forceinline__ uint32_t packh(float lo, float hi) {
    uint32_t r;
    asm("cvt.rn.f16x2.f32 %0, %1, %2;" : "=r"(r) : "f"(hi), "f"(lo));
    return r;
}

// fp32-accumulator HMMA (hi pass)
#define MMA_F16(d, a, b)                                                      \
    asm volatile(                                                             \
        "mma.sync.aligned.m16n8k16.row.col.f32.f16.f16.f32 "                  \
        "{%0,%1,%2,%3}, {%4,%5,%6,%7}, {%8,%9}, {%0,%1,%2,%3};\n"             \
        : "+f"((d)[0]), "+f"((d)[1]), "+f"((d)[2]), "+f"((d)[3])              \
        : "r"((a)[0]), "r"((a)[1]), "r"((a)[2]), "r"((a)[3]),                 \
          "r"((b)[0]), "r"((b)[1]))

// fp16-accumulator HMMA (lo pass) — tests the half-rate-f32acc hypothesis
#define MMA_F16ACC(d, a, b)                                                   \
    asm volatile(                                                             \
        "mma.sync.aligned.m16n8k16.row.col.f16.f16.f16.f16 "                  \
        "{%0,%1}, {%2,%3,%4,%5}, {%6,%7}, {%0,%1};\n"                         \
        : "+r"((d)[0]), "+r"((d)[1])                                          \
        : "r"((a)[0]), "r"((a)[1]), "r"((a)[2]), "r"((a)[3]),                 \
          "r"((b)[0]), "r"((b)[1]))

#define LDSM_X4(r, addr)                                                      \
    asm volatile("ldmatrix.sync.aligned.m8n8.x4.shared.b16 {%0,%1,%2,%3}, [%4];" \
                 : "=r"((r)[0]), "=r"((r)[1]), "=r"((r)[2]), "=r"((r)[3])     \
                 : "r"(addr))

#define LDSM_X4T(r, addr)                                                     \
    asm volatile("ldmatrix.sync.aligned.m8n8.x4.trans.shared.b16 {%0,%1,%2,%3}, [%4];" \
                 : "=r"((r)[0]), "=r"((r)[1]), "=r"((r)[2]), "=r"((r)[3])     \
                 : "r"(addr))

#define CP_ASYNC16(dst, src)                                                  \
    asm volatile("cp.async.cg.shared.global [%0], [%1], 16;" ::               \
                 "r"(dst), "l"(src))
#define CP_COMMIT() asm volatile("cp.async.commit_group;" ::: "memory")
#define CP_WAIT1()  asm volatile("cp.async.wait_group 1;" ::: "memory")
#define CP_WAIT0()  asm volatile("cp.async.wait_group 0;" ::: "memory")

// ---------------------------------------------------------------------------
// Prep: split fp32 -> fp16 hi/lo, and plain fp32 -> fp16 convert.
// ---------------------------------------------------------------------------
__global__ __launch_bounds__(256)
void split_kernel(const float* __restrict__ src, h16* __restrict__ h,
                  h16* __restrict__ l, int n4) {
    int i = blockIdx.x * 256 + threadIdx.x;
    if (i >= n4) return;
    float4 v = *(const float4*)&src[(size_t)i * 4];
    float f[4] = {v.x, v.y, v.z, v.w};
    float hf[4], lf[4];
#pragma unroll
    for (int e = 0; e < 4; e++) {
        hf[e] = __half2float(__float2half_rn(f[e]));
        lf[e] = f[e] - hf[e];
    }
    *(uint2*)&h[(size_t)i * 4] = make_uint2(packh(hf[0], hf[1]), packh(hf[2], hf[3]));
    *(uint2*)&l[(size_t)i * 4] = make_uint2(packh(lf[0], lf[1]), packh(lf[2], lf[3]));
}

__global__ __launch_bounds__(256)
void conv_kernel(const float* __restrict__ src, h16* __restrict__ dst, int n4) {
    int i = blockIdx.x * 256 + threadIdx.x;
    if (i >= n4) return;
    float4 v = *(const float4*)&src[(size_t)i * 4];
    *(uint2*)&dst[(size_t)i * 4] = make_uint2(packh(v.x, v.y), packh(v.z, v.w));
}

// ---------------------------------------------------------------------------
// 2-pass fp16 GEMM: hi pass f32-accum, lo pass f16-accum.
// BM=BN=128, BK=32/stage, 3-stage cp.async, 1 barrier/stage.
// 512 thr = 16 warps (4M x 4N), warp tile 32x32.
// ---------------------------------------------------------------------------
#define GST 40                        // halfs per row (32 + 8 pad)
#define ARRB (128 * GST * 2)          // 10240 bytes per array
#define STGB (3 * ARRB)               // 30720 bytes per stage
#define GSMEM (3 * STGB)              // 92160 (3 stages)

template <int MODE>
__global__ __launch_bounds__(512, 1)
void gemm_f16_kernel(const h16* __restrict__ Agh, const h16* __restrict__ Agl,
                     const h16* __restrict__ Bgf, float* __restrict__ Cout) {
    extern __shared__ char smem[];
    const uint32_t sbase = s2u(smem);
    const int m0 = blockIdx.y * 128;
    const int n0 = blockIdx.x * 128;
    const int tid = threadIdx.x;
    const int lane = tid & 31;
    const int warp = tid >> 5;
    const int warpM = warp & 3;    // 4 M x 32 rows
    const int warpN = warp >> 2;   // 4 N x 32 cols

    const int g = lane >> 2;
    const int qp = lane & 3;
    const int frow = lane & 15;
    const int fcol = (lane >> 4) << 3;

    float Chi[2][4][4];
    uint32_t Clo[2][4][2];
#pragma unroll
    for (int mt = 0; mt < 2; mt++)
#pragma unroll
        for (int nt = 0; nt < 4; nt++) {
#pragma unroll
            for (int r = 0; r < 4; r++) Chi[mt][nt][r] = 0.f;
            Clo[mt][nt][0] = 0u;
            Clo[mt][nt][1] = 0u;
        }

    // per stage: 3 arrays x 512 chunks of 16B; each of 512 threads: 1 chunk/array
#define ISSUE(s)                                                              \
    do {                                                                      \
        const int k0_ = (s) * 32;                                             \
        const uint32_t sb_ = sbase + ((s) % 3) * STGB;                        \
        int row = tid >> 2;                                                   \
        int q = (tid & 3) * 8;                                                \
        uint32_t soff = (row * GST + q) * 2;                                  \
        size_t ga = (size_t)(m0 + row) * KDIM + k0_ + q;                      \
        size_t gb = (size_t)(n0 + row) * KDIM + k0_ + q;                      \
        CP_ASYNC16(sb_ + soff,            Agh + ga);                          \
        CP_ASYNC16(sb_ + ARRB + soff,     Agl + ga);                          \
        CP_ASYNC16(sb_ + 2 * ARRB + soff, Bgf + gb);                          \
        CP_COMMIT();                                                          \
    } while (0)

    ISSUE(0);
    ISSUE(1);

    const int NST = KDIM / 32;   // 64
#pragma unroll 1
    for (int s = 0; s < NST; s++) {
        if (s == NST - 1) CP_WAIT0(); else CP_WAIT1();
        __syncthreads();
        if (s + 2 < NST) ISSUE(s + 2);

        const uint32_t uAh = sbase + (s % 3) * STGB;
        const uint32_t uAl = uAh + ARRB;
        const uint32_t uBf = uAh + 2 * ARRB;

#pragma unroll
        for (int kc = 0; kc < 2; kc++) {
            const int col = kc * 16 + fcol;
            uint32_t a_hi[2][4], a_lo[2][4];
#pragma unroll
            for (int mt = 0; mt < 2; mt++) {
                uint32_t off = ((warpM * 32 + mt * 16 + frow) * GST + col) * 2;
                LDSM_X4(a_hi[mt], uAh + off);
                LDSM_X4(a_lo[mt], uAl + off);
            }
#pragma unroll
            for (int p = 0; p < 2; p++) {
                uint32_t off = ((warpN * 32 + p * 16 + frow) * GST + col) * 2;
                uint32_t kb[4];
                LDSM_X4(kb, uBf + off);
                uint32_t b0[2] = {kb[0], kb[2]};
                uint32_t b1[2] = {kb[1], kb[3]};
#pragma unroll
                for (int mt = 0; mt < 2; mt++) {
                    MMA_F16(Chi[mt][2 * p], a_hi[mt], b0);
                    MMA_F16(Chi[mt][2 * p + 1], a_hi[mt], b1);
                    MMA_F16ACC(Clo[mt][2 * p], a_lo[mt], b0);
                    MMA_F16ACC(Clo[mt][2 * p + 1], a_lo[mt], b1);
                }
            }
        }
    }
#undef ISSUE

    // ---- epilogue: C = Chi + float(Clo) ----
#pragma unroll
    for (int mt = 0; mt < 2; mt++) {
#pragma unroll
        for (int nt = 0; nt < 4; nt++) {
            float2 lo0 = __half22float2(*(const __half2*)&Clo[mt][nt][0]);
            float2 lo1 = __half22float2(*(const __half2*)&Clo[mt][nt][1]);
            float2 v0 = make_float2(Chi[mt][nt][0] + lo0.x, Chi[mt][nt][1] + lo0.y);
            float2 v1 = make_float2(Chi[mt][nt][2] + lo1.x, Chi[mt][nt][3] + lo1.y);
            int gm0 = m0 + warpM * 32 + mt * 16 + g;
            int gn = n0 + warpN * 32 + nt * 8 + qp * 2;
            if (MODE == 0) {
                int which = gn >> 11;
                int rem = gn & 2047;
                int h = rem >> 7;
                int d = rem & 127;
#pragma unroll
                for (int rr = 0; rr < 2; rr++) {
                    int gm = gm0 + rr * 8;
                    int b = gm >> 11;
                    int s = gm & 2047;
                    size_t off = (size_t)which * ((size_t)BNHS * HD_) +
                                 (((size_t)(b * NH_ + h)) * S_ + s) * HD_ + d;
                    *(float2*)&g_qkv[off] = rr ? v1 : v0;
                }
            } else {
                *(float2*)&Cout[(size_t)gm0 * HID_ + gn] = v0;
                *(float2*)&Cout[(size_t)(gm0 + 8) * HID_ + gn] = v1;
            }
        }
    }
}

// ---------------------------------------------------------------------------
// RoPE + convert: Q -> (qh, ql) fp16 split; K -> kf fp16; V -> vf fp16.
// ---------------------------------------------------------------------------
__global__ __launch_bounds__(256)
void rope_conv_kernel(const float* __restrict__ cosT, const float* __restrict__ sinT) {
    long long t = (long long)blockIdx.x * 256 + threadIdx.x;
    int d = (int)(t & 63);
    long long row = t >> 6;                 // 0 .. 3*BNHS-1
    int which = (int)(row / BNHS);
    long long lr = row % BNHS;
    int s = (int)(lr % S_);
    const float* p = g_qkv + row * HD_;
    float x1 = p[d];
    float x2 = p[d + 64];

    if (which < 2) {
        float c1 = cosT[s * HD_ + d];
        float s1 = sinT[s * HD_ + d];
        float c2 = cosT[s * HD_ + d + 64];
        float s2 = sinT[s * HD_ + d + 64];
        float r1 = x1 * c1 - x2 * s1;
        float r2 = x2 * c2 + x1 * s2;
        if (which == 0) {
            float h1 = __half2float(__float2half_rn(r1));
            float h2 = __half2float(__float2half_rn(r2));
            g_qh[lr * HD_ + d] = __float2half_rn(r1);
            g_ql[lr * HD_ + d] = __float2half_rn(r1 - h1);
            g_qh[lr * HD_ + d + 64] = __float2half_rn(r2);
            g_ql[lr * HD_ + d + 64] = __float2half_rn(r2 - h2);
        } else {
            g_kf[lr * HD_ + d] = __float2half_rn(r1);
            g_kf[lr * HD_ + d + 64] = __float2half_rn(r2);
        }
    } else {
        g_vf[lr * HD_ + d] = __float2half_rn(x1);
        g_vf[lr * HD_ + d + 64] = __float2half_rn(x2);
    }
}

// ---------------------------------------------------------------------------
// 2-pass fp16 causal flash attention, cp.async K/V double buffer.
// BQ=128, BK=64, 256 threads. (unchanged from R13)
// ---------------------------------------------------------------------------
#define STQ 136
#define KVB (64 * STQ * 2)
#define ATTN_SMEM ((2 * 128) * STQ * 2 + 4 * KVB)

__global__ __launch_bounds__(256, 1)
void attn_mma_kernel() {
    extern __shared__ char smraw[];
    h16* sQh = (h16*)smraw;
    h16* sQl = sQh + 128 * STQ;
    char* kvbase = (char*)(sQl + 128 * STQ);
    const uint32_t ukv = s2u(kvbase);

    const int tid = threadIdx.x;
    const int lane = tid & 31;
    const int w = tid >> 5;
    const int qp = lane & 3;
    const int g = lane >> 2;
    const int frow = lane & 15;
    const int fcol = (lane >> 4) << 3;

    const int qt = blockIdx.x;
    const int bh = blockIdx.y;
    const int b = bh >> 4;
    const int h = bh & 15;
    const int q0 = qt * 128;

    const size_t hs = (size_t)S_ * HD_;
    const h16* Qh = g_qh + (size_t)bh * hs;
    const h16* Ql = g_ql + (size_t)bh * hs;
    const h16* Kf = g_kf + (size_t)bh * hs;
    const h16* Vf = g_vf + (size_t)bh * hs;

#pragma unroll
    for (int i = 0; i < 8; i++) {
        int idx = tid + i * 256;
        int r = idx >> 4;
        int dd = (idx & 15) * 8;
        size_t ga = (size_t)(q0 + r) * HD_ + dd;
        *(uint4*)&sQh[r * STQ + dd] = *(const uint4*)&Qh[ga];
        *(uint4*)&sQl[r * STQ + dd] = *(const uint4*)&Ql[ga];
    }

    const uint32_t uQh = s2u(sQh), uQl = s2u(sQl);

    float O[16][4];
#pragma unroll
    for (int t = 0; t < 16; t++)
#pragma unroll
        for (int r = 0; r < 4; r++) O[t][r] = 0.f;
    float m0 = -1e30f, m1 = -1e30f, l0 = 0.f, l1 = 0.f;

    const float sc = 0.08838834764831845f;
    const int row0 = q0 + w * 16 + g;
    const int row1 = row0 + 8;

#define KV_ISSUE(kt_)                                                         \
    do {                                                                      \
        const int kk0 = (kt_) * 64;                                           \
        const uint32_t kb_ = ukv + ((kt_) & 1) * (2 * KVB);                   \
        _Pragma("unroll")                                                     \
        for (int t = 0; t < 4; t++) {                                         \
            int idx = tid + t * 256;                                          \
            int r = idx >> 4;                                                 \
            int dd = (idx & 15) * 8;                                          \
            uint32_t soff = (r * STQ + dd) * 2;                               \
            size_t ga = (size_t)(kk0 + r) * HD_ + dd;                         \
            CP_ASYNC16(kb_ + soff,       Kf + ga);                            \
            CP_ASYNC16(kb_ + KVB + soff, Vf + ga);                            \
        }                                                                     \
        CP_COMMIT();                                                          \
    } while (0)

    KV_ISSUE(0);

    const int ktn = (q0 + 128) >> 6;
#pragma unroll 1
    for (int kt = 0; kt < ktn; kt++) {
        const int k0 = kt * 64;
        CP_WAIT0();
        __syncthreads();
        if (kt + 1 < ktn) KV_ISSUE(kt + 1);

        const uint32_t uKf = ukv + (kt & 1) * (2 * KVB);
        const uint32_t uVf = uKf + KVB;

        const bool active = (k0 <= q0 + w * 16 + 15);
        if (active) {
            float S[8][4];
#pragma unroll
            for (int t = 0; t < 8; t++)
#pragma unroll
                for (int r = 0; r < 4; r++) S[t][r] = 0.f;

#pragma unroll
            for (int kc = 0; kc < 8; kc++) {
                const int col = kc * 16 + fcol;
                uint32_t qh[4], ql[4];
                uint32_t qoff = ((w * 16 + frow) * STQ + col) * 2;
                LDSM_X4(qh, uQh + qoff);
                LDSM_X4(ql, uQl + qoff);
#pragma unroll
                for (int p = 0; p < 4; p++) {
                    uint32_t koff = ((p * 16 + frow) * STQ + col) * 2;
                    uint32_t kf[4];
                    LDSM_X4(kf, uKf + koff);
                    uint32_t b0[2] = {kf[0], kf[2]};
                    uint32_t b1[2] = {kf[1], kf[3]};
                    MMA_F16(S[2 * p], qh, b0);
                    MMA_F16(S[2 * p + 1], qh, b1);
                    MMA_F16(S[2 * p], ql, b0);
                    MMA_F16(S[2 * p + 1], ql, b1);
                }
            }

            const bool maskneed = (k0 + 63 > row0);
#pragma unroll
            for (int t = 0; t < 8; t++) {
                int c0 = k0 + 8 * t + 2 * qp;
#pragma unroll
                for (int r = 0; r < 4; r++) {
                    S[t][r] *= sc;
                    if (maskneed) {
                        int colg = c0 + (r & 1);
                        int rowg = (r < 2) ? row0 : row1;
                        if (colg > rowg) S[t][r] = -1e9f;
                    }
                }
            }

            float rm0 = -1e30f, rm1 = -1e30f;
#pragma unroll
            for (int t = 0; t < 8; t++) {
                rm0 = fmaxf(rm0, fmaxf(S[t][0], S[t][1]));
                rm1 = fmaxf(rm1, fmaxf(S[t][2], S[t][3]));
            }
            rm0 = fmaxf(rm0, __shfl_xor_sync(0xffffffffu, rm0, 1));
            rm0 = fmaxf(rm0, __shfl_xor_sync(0xffffffffu, rm0, 2));
            rm1 = fmaxf(rm1, __shfl_xor_sync(0xffffffffu, rm1, 1));
            rm1 = fmaxf(rm1, __shfl_xor_sync(0xffffffffu, rm1, 2));
            float mn0 = fmaxf(m0, rm0), mn1 = fmaxf(m1, rm1);
            float a0 = __expf(m0 - mn0), a1 = __expf(m1 - mn1);
            float rs0 = 0.f, rs1 = 0.f;
#pragma unroll
            for (int t = 0; t < 8; t++) {
                S[t][0] = __expf(S[t][0] - mn0);
                S[t][1] = __expf(S[t][1] - mn0);
                S[t][2] = __expf(S[t][2] - mn1);
                S[t][3] = __expf(S[t][3] - mn1);
                rs0 += S[t][0] + S[t][1];
                rs1 += S[t][2] + S[t][3];
            }
            rs0 += __shfl_xor_sync(0xffffffffu, rs0, 1);
            rs0 += __shfl_xor_sync(0xffffffffu, rs0, 2);
            rs1 += __shfl_xor_sync(0xffffffffu, rs1, 1);
            rs1 += __shfl_xor_sync(0xffffffffu, rs1, 2);
            l0 = l0 * a0 + rs0;
            l1 = l1 * a1 + rs1;
            m0 = mn0;
            m1 = mn1;
#pragma unroll
            for (int t = 0; t < 16; t++) {
                O[t][0] *= a0; O[t][1] *= a0;
                O[t][2] *= a1; O[t][3] *= a1;
            }

            uint32_t ph[4][4], pl[4][4];
#pragma unroll
            for (int kc2 = 0; kc2 < 4; kc2++) {
                int t0 = 2 * kc2, t1 = 2 * kc2 + 1;
                float src[8] = {S[t0][0], S[t0][1], S[t0][2], S[t0][3],
                                S[t1][0], S[t1][1], S[t1][2], S[t1][3]};
                float hv[8], lv[8];
#pragma unroll
                for (int e = 0; e < 8; e++) {
                    hv[e] = __half2float(__float2half_rn(src[e]));
                    lv[e] = src[e] - hv[e];
                }
                ph[kc2][0] = packh(hv[0], hv[1]);
                ph[kc2][1] = packh(hv[2], hv[3]);
                ph[kc2][2] = packh(hv[4], hv[5]);
                ph[kc2][3] = packh(hv[6], hv[7]);
                pl[kc2][0] = packh(lv[0], lv[1]);
                pl[kc2][1] = packh(lv[2], lv[3]);
                pl[kc2][2] = packh(lv[4], lv[5]);
                pl[kc2][3] = packh(lv[6], lv[7]);
            }

#pragma unroll
            for (int kc2 = 0; kc2 < 4; kc2++) {
#pragma unroll
                for (int p = 0; p < 8; p++) {
                    uint32_t voff = ((kc2 * 16 + frow) * STQ + p * 16 + fcol) * 2;
                    uint32_t vf[4];
                    LDSM_X4T(vf, uVf + voff);
                    uint32_t b0[2] = {vf[0], vf[1]};
                    uint32_t b1[2] = {vf[2], vf[3]};
                    MMA_F16(O[2 * p], ph[kc2], b0);
                    MMA_F16(O[2 * p + 1], ph[kc2], b1);
                    MMA_F16(O[2 * p], pl[kc2], b0);
                    MMA_F16(O[2 * p + 1], pl[kc2], b1);
                }
            }
        }
    }
#undef KV_ISSUE

    // ---- normalize + write pre-split ctx [b][s][h][d] ----
    float inv0 = 1.f / l0, inv1 = 1.f / l1;
    size_t base0 = (((size_t)b * S_ + row0) * NH_ + h) * HD_;
    size_t base1 = (((size_t)b * S_ + row1) * NH_ + h) * HD_;
#pragma unroll
    for (int t = 0; t < 16; t++) {
        int d = 8 * t + 2 * qp;
        float o0 = O[t][0] * inv0, o1 = O[t][1] * inv0;
        float o2 = O[t][2] * inv1, o3 = O[t][3] * inv1;
        float h0 = __half2float(__float2half_rn(o0));
        float h1 = __half2float(__float2half_rn(o1));
        float h2 = __half2float(__float2half_rn(o2));
        float h3 = __half2float(__float2half_rn(o3));
        *(uint32_t*)&g_ctxh[base0 + d] = packh(h0, h1);
        *(uint32_t*)&g_ctxl[base0 + d] = packh(o0 - h0, o1 - h1);
        *(uint32_t*)&g_ctxh[base1 + d] = packh(h2, h3);
        *(uint32_t*)&g_ctxl[base1 + d] = packh(o2 - h2, o3 - h3);
    }
}

// ---------------------------------------------------------------------------
extern "C" void kernel_launch(void* const* d_in, const int* in_sizes, int n_in,
                              void* d_out, int out_size) {
    (void)in_sizes; (void)n_in; (void)out_size;
    const float* x     = (const float*)d_in[0];
    const float* w_qkv = (const float*)d_in[1];
    const float* w_o   = (const float*)d_in[2];
    const float* cosT  = (const float*)d_in[3];
    const float* sinT  = (const float*)d_in[4];
    float* out = (float*)d_out;

    cudaFuncSetAttribute(attn_mma_kernel, cudaFuncAttributeMaxDynamicSharedMemorySize, ATTN_SMEM);
    cudaFuncSetAttribute(gemm_f16_kernel<0>, cudaFuncAttributeMaxDynamicSharedMemorySize, GSMEM);
    cudaFuncSetAttribute(gemm_f16_kernel<1>, cudaFuncAttributeMaxDynamicSharedMemorySize, GSMEM);

    h16 *xh, *xl, *wqf, *wof, *ctxh, *ctxl;
    cudaGetSymbolAddress((void**)&xh, g_xh);
    cudaGetSymbolAddress((void**)&xl, g_xl);
    cudaGetSymbolAddress((void**)&wqf, g_wqf);
    cudaGetSymbolAddress((void**)&wof, g_wof);
    cudaGetSymbolAddress((void**)&ctxh, g_ctxh);
    cudaGetSymbolAddress((void**)&ctxl, g_ctxl);

    int n4x = (B_ * S_ * HID_) / 4;
    int n4q = (3 * HID_ * HID_) / 4;
    int n4o = (HID_ * HID_) / 4;

    split_kernel<<<(n4x + 255) / 256, 256>>>(x, xh, xl, n4x);
    conv_kernel<<<(n4q + 255) / 256, 256>>>(w_qkv, wqf, n4q);
    conv_kernel<<<(n4o + 255) / 256, 256>>>(w_o, wof, n4o);

    // 1) QKV projection: grid (N/128, M/128), 512 threads
    gemm_f16_kernel<0><<<dim3(6144 / 128, 4096 / 128), 512, GSMEM>>>(xh, xl, wqf, nullptr);

    // 2) RoPE + convert
    rope_conv_kernel<<<(3 * BNHS * 64) / 256, 256>>>(cosT, sinT);

    // 3) Flash attention
    attn_mma_kernel<<<dim3(S_ / 128, B_ * NH_), 256, ATTN_SMEM>>>();

    // 4) Output projection
    gemm_f16_kernel<1><<<dim3(2048 / 128, 4096 / 128), 512, GSMEM>>>(ctxh, ctxl, wof, out);
}

// round 16
// speedup vs baseline: 1.2872x; 1.2872x over previous
#include <cuda_runtime.h>
#include <cuda_fp16.h>
#include <cstdint>
#include <math.h>

#define B_   2
#define S_   2048
#define HID_ 2048
#define NH_  16
#define HD_  128
#define KDIM 2048
#define BNHS (B_ * NH_ * S_)

typedef __half h16;

// ---- persistent buffers ----
__device__ float g_qkv[(size_t)3 * BNHS * HD_];   // [which][b][h][s][d] fp32
__device__ h16 g_xh[(size_t)B_ * S_ * HID_];
__device__ h16 g_xl[(size_t)B_ * S_ * HID_];
__device__ h16 g_wqf[(size_t)3 * HID_ * HID_];
__device__ h16 g_wof[(size_t)HID_ * HID_];
__device__ h16 g_qh[(size_t)BNHS * HD_];
__device__ h16 g_ql[(size_t)BNHS * HD_];
__device__ h16 g_kf[(size_t)BNHS * HD_];
__device__ h16 g_vf[(size_t)BNHS * HD_];
__device__ h16 g_ctxh[(size_t)B_ * S_ * HID_];    // [b][s][h][d]
__device__ h16 g_ctxl[(size_t)B_ * S_ * HID_];

// ---------------- helpers ----------------
__device__ __forceinline__ uint32_t s2u(const void* p) {
    return (uint32_t)__cvta_generic_to_shared(p);
}
__device__ __forceinline__ uint32_t packh(float lo, float hi) {
    uint32_t r;
    asm("cvt.rn.f16x2.f32 %0, %1, %2;" : "=r"(r) : "f"(hi), "f"(lo));
    return r;
}

#define MMA_F16(d, a, b)                                                      \
    asm volatile(                                                             \
        "mma.sync.aligned.m16n8k16.row.col.f32.f16.f16.f32 "                  \
        "{%0,%1,%2,%3}, {%4,%5,%6,%7}, {%8,%9}, {%0,%1,%2,%3};\n"             \
        : "+f"((d)[0]), "+f"((d)[1]), "+f"((d)[2]), "+f"((d)[3])              \
        : "r"((a)[0]), "r"((a)[1]), "r"((a)[2]), "r"((a)[3]),                 \
          "r"((b)[0]), "r"((b)[1]))

#define LDSM_X4(r, addr)                                                      \
    asm volatile("ldmatrix.sync.aligned.m8n8.x4.shared.b16 {%0,%1,%2,%3}, [%4];" \
                 : "=r"((r)[0]), "=r"((r)[1]), "=r"((r)[2]), "=r"((r)[3])     \
                 : "r"(addr))

#define LDSM_X4T(r, addr)                                                     \
    asm volatile("ldmatrix.sync.aligned.m8n8.x4.trans.shared.b16 {%0,%1,%2,%3}, [%4];" \
                 : "=r"((r)[0]), "=r"((r)[1]), "=r"((r)[2]), "=r"((r)[3])     \
                 : "r"(addr))

#define CP_ASYNC16(dst, src)                                                  \
    asm volatile("cp.async.cg.shared.global [%0], [%1], 16;" ::               \
                 "r"(dst), "l"(src))
#define CP_COMMIT() asm volatile("cp.async.commit_group;" ::: "memory")
#define CP_WAIT1()  asm volatile("cp.async.wait_group 1;" ::: "memory")
#define CP_WAIT0()  asm volatile("cp.async.wait_group 0;" ::: "memory")

// ---------------------------------------------------------------------------
// Prep: split fp32 -> fp16 hi/lo, and plain fp32 -> fp16 convert.
// ---------------------------------------------------------------------------
__global__ __launch_bounds__(256)
void split_kernel(const float* __restrict__ src, h16* __restrict__ h,
                  h16* __restrict__ l, int n4) {
    int i = blockIdx.x * 256 + threadIdx.x;
    if (i >= n4) return;
    float4 v = *(const float4*)&src[(size_t)i * 4];
    float f[4] = {v.x, v.y, v.z, v.w};
    float hf[4], lf[4];
#pragma unroll
    for (int e = 0; e < 4; e++) {
        hf[e] = __half2float(__float2half_rn(f[e]));
        lf[e] = f[e] - hf[e];
    }
    *(uint2*)&h[(size_t)i * 4] = make_uint2(packh(hf[0], hf[1]), packh(hf[2], hf[3]));
    *(uint2*)&l[(size_t)i * 4] = make_uint2(packh(lf[0], lf[1]), packh(lf[2], lf[3]));
}

__global__ __launch_bounds__(256)
void conv_kernel(const float* __restrict__ src, h16* __restrict__ dst, int n4) {
    int i = blockIdx.x * 256 + threadIdx.x;
    if (i >= n4) return;
    float4 v = *(const float4*)&src[(size_t)i * 4];
    *(uint2*)&dst[(size_t)i * 4] = make_uint2(packh(v.x, v.y), packh(v.z, v.w));
}

// ---------------------------------------------------------------------------
// fp16 GEMM (R13 pipeline): BM=BN=128, BK=32/stage, 3-stage cp.async,
// 1 barrier/stage, 256 thr, 8 warps (4Mx2N), warp tile 32x64.
// PASSES=2: A = Ah + Al (2 HMMA passes). PASSES=1: A = Ah only.
// MODE 0: scatter fp32 q/k/v into g_qkv (gn offset by nbase). MODE 1: fp32 out.
// ---------------------------------------------------------------------------
#define GST 40                        // halfs per row (32 + 8 pad)
#define ARRB (128 * GST * 2)          // 10240 bytes per array
#define STGB (3 * ARRB)               // 30720 bytes per stage
#define GSMEM (3 * STGB)              // 92160 (3 stages)

template <int MODE, int PASSES>
__global__ __launch_bounds__(256, 2)
void gemm_f16_kernel(const h16* __restrict__ Agh, const h16* __restrict__ Agl,
                     const h16* __restrict__ Bgf, float* __restrict__ Cout,
                     int nbase) {
    extern __shared__ char smem[];
    const uint32_t sbase = s2u(smem);
    const int m0 = blockIdx.y * 128;
    const int n0 = blockIdx.x * 128;   // within this launch's B slice
    const int tid = threadIdx.x;
    const int lane = tid & 31;
    const int warp = tid >> 5;
    const int warpM = warp & 3;
    const int warpN = warp >> 2;

    const int g = lane >> 2;
    const int qp = lane & 3;
    const int frow = lane & 15;
    const int fcol = (lane >> 4) << 3;

    float C[2][8][4];
#pragma unroll
    for (int mt = 0; mt < 2; mt++)
#pragma unroll
        for (int nt = 0; nt < 8; nt++)
#pragma unroll
            for (int r = 0; r < 4; r++) C[mt][nt][r] = 0.f;

#define ISSUE(s)                                                              \
    do {                                                                      \
        const int k0_ = (s) * 32;                                             \
        const uint32_t sb_ = sbase + ((s) % 3) * STGB;                        \
        _Pragma("unroll")                                                     \
        for (int t = 0; t < 2; t++) {                                         \
            int idx = tid + t * 256;                                          \
            int row = idx >> 2;                                               \
            int qtr = (idx & 3) * 8;                                          \
            uint32_t soff = (row * GST + qtr) * 2;                            \
            size_t ga = (size_t)(m0 + row) * KDIM + k0_ + qtr;                \
            size_t gb = (size_t)(n0 + row) * KDIM + k0_ + qtr;                \
            CP_ASYNC16(sb_ + soff, Agh + ga);                                 \
            if (PASSES == 2) CP_ASYNC16(sb_ + ARRB + soff, Agl + ga);         \
            CP_ASYNC16(sb_ + 2 * ARRB + soff, Bgf + gb);                      \
        }                                                                     \
        CP_COMMIT();                                                          \
    } while (0)

    ISSUE(0);
    ISSUE(1);

    const int NST = KDIM / 32;   // 64
#pragma unroll 1
    for (int s = 0; s < NST; s++) {
        if (s == NST - 1) CP_WAIT0(); else CP_WAIT1();
        __syncthreads();
        if (s + 2 < NST) ISSUE(s + 2);

        const uint32_t uAh = sbase + (s % 3) * STGB;
        const uint32_t uAl = uAh + ARRB;
        const uint32_t uBf = uAh + 2 * ARRB;

#pragma unroll
        for (int kc = 0; kc < 2; kc++) {
            const int col = kc * 16 + fcol;
            uint32_t a_hi[2][4], a_lo[2][4];
#pragma unroll
            for (int mt = 0; mt < 2; mt++) {
                uint32_t off = ((warpM * 32 + mt * 16 + frow) * GST + col) * 2;
                LDSM_X4(a_hi[mt], uAh + off);
                if (PASSES == 2) LDSM_X4(a_lo[mt], uAl + off);
            }
#pragma unroll
            for (int p = 0; p < 4; p++) {
                uint32_t off = ((warpN * 64 + p * 16 + frow) * GST + col) * 2;
                uint32_t kb[4];
                LDSM_X4(kb, uBf + off);
                uint32_t b0[2] = {kb[0], kb[2]};
                uint32_t b1[2] = {kb[1], kb[3]};
#pragma unroll
                for (int mt = 0; mt < 2; mt++) {
                    MMA_F16(C[mt][2 * p], a_hi[mt], b0);
                    MMA_F16(C[mt][2 * p + 1], a_hi[mt], b1);
                    if (PASSES == 2) {
                        MMA_F16(C[mt][2 * p], a_lo[mt], b0);
                        MMA_F16(C[mt][2 * p + 1], a_lo[mt], b1);
                    }
                }
            }
        }
    }
#undef ISSUE

    // ---- epilogue ----
#pragma unroll
    for (int mt = 0; mt < 2; mt++) {
#pragma unroll
        for (int nt = 0; nt < 8; nt++) {
            int gm0 = m0 + warpM * 32 + mt * 16 + g;
            int gn = nbase + n0 + warpN * 64 + nt * 8 + qp * 2;
            float2 v0 = make_float2(C[mt][nt][0], C[mt][nt][1]);
            float2 v1 = make_float2(C[mt][nt][2], C[mt][nt][3]);
            if (MODE == 0) {
                int which = gn >> 11;
                int rem = gn & 2047;
                int h = rem >> 7;
                int d = rem & 127;
#pragma unroll
                for (int rr = 0; rr < 2; rr++) {
                    int gm = gm0 + rr * 8;
                    int b = gm >> 11;
                    int s = gm & 2047;
                    size_t off = (size_t)which * ((size_t)BNHS * HD_) +
                                 (((size_t)(b * NH_ + h)) * S_ + s) * HD_ + d;
                    *(float2*)&g_qkv[off] = rr ? v1 : v0;
                }
            } else {
                *(float2*)&Cout[(size_t)gm0 * HID_ + gn] = v0;
                *(float2*)&Cout[(size_t)(gm0 + 8) * HID_ + gn] = v1;
            }
        }
    }
}

// ---------------------------------------------------------------------------
// RoPE + convert: Q -> (qh, ql) fp16 split; K -> kf fp16; V -> vf fp16.
// ---------------------------------------------------------------------------
__global__ __launch_bounds__(256)
void rope_conv_kernel(const float* __restrict__ cosT, const float* __restrict__ sinT) {
    long long t = (long long)blockIdx.x * 256 + threadIdx.x;
    int d = (int)(t & 63);
    long long row = t >> 6;                 // 0 .. 3*BNHS-1
    int which = (int)(row / BNHS);
    long long lr = row % BNHS;
    int s = (int)(lr % S_);
    const float* p = g_qkv + row * HD_;
    float x1 = p[d];
    float x2 = p[d + 64];

    if (which < 2) {
        float c1 = cosT[s * HD_ + d];
        float s1 = sinT[s * HD_ + d];
        float c2 = cosT[s * HD_ + d + 64];
        float s2 = sinT[s * HD_ + d + 64];
        float r1 = x1 * c1 - x2 * s1;
        float r2 = x2 * c2 + x1 * s2;
        if (which == 0) {
            float h1 = __half2float(__float2half_rn(r1));
            float h2 = __half2float(__float2half_rn(r2));
            g_qh[lr * HD_ + d] = __float2half_rn(r1);
            g_ql[lr * HD_ + d] = __float2half_rn(r1 - h1);
            g_qh[lr * HD_ + d + 64] = __float2half_rn(r2);
            g_ql[lr * HD_ + d + 64] = __float2half_rn(r2 - h2);
        } else {
            g_kf[lr * HD_ + d] = __float2half_rn(r1);
            g_kf[lr * HD_ + d + 64] = __float2half_rn(r2);
        }
    } else {
        g_vf[lr * HD_ + d] = __float2half_rn(x1);
        g_vf[lr * HD_ + d + 64] = __float2half_rn(x2);
    }
}

// ---------------------------------------------------------------------------
// 2-pass fp16 causal flash attention, cp.async K/V double buffer.
// BQ=128, BK=64, 256 threads. (R13)
// ---------------------------------------------------------------------------
#define STQ 136
#define KVB (64 * STQ * 2)
#define ATTN_SMEM ((2 * 128) * STQ * 2 + 4 * KVB)

__global__ __launch_bounds__(256, 1)
void attn_mma_kernel() {
    extern __shared__ char smraw[];
    h16* sQh = (h16*)smraw;
    h16* sQl = sQh + 128 * STQ;
    char* kvbase = (char*)(sQl + 128 * STQ);
    const uint32_t ukv = s2u(kvbase);

    const int tid = threadIdx.x;
    const int lane = tid & 31;
    const int w = tid >> 5;
    const int qp = lane & 3;
    const int g = lane >> 2;
    const int frow = lane & 15;
    const int fcol = (lane >> 4) << 3;

    const int qt = blockIdx.x;
    const int bh = blockIdx.y;
    const int b = bh >> 4;
    const int h = bh & 15;
    const int q0 = qt * 128;

    const size_t hs = (size_t)S_ * HD_;
    const h16* Qh = g_qh + (size_t)bh * hs;
    const h16* Ql = g_ql + (size_t)bh * hs;
    const h16* Kf = g_kf + (size_t)bh * hs;
    const h16* Vf = g_vf + (size_t)bh * hs;

#pragma unroll
    for (int i = 0; i < 8; i++) {
        int idx = tid + i * 256;
        int r = idx >> 4;
        int dd = (idx & 15) * 8;
        size_t ga = (size_t)(q0 + r) * HD_ + dd;
        *(uint4*)&sQh[r * STQ + dd] = *(const uint4*)&Qh[ga];
        *(uint4*)&sQl[r * STQ + dd] = *(const uint4*)&Ql[ga];
    }

    const uint32_t uQh = s2u(sQh), uQl = s2u(sQl);

    float O[16][4];
#pragma unroll
    for (int t = 0; t < 16; t++)
#pragma unroll
        for (int r = 0; r < 4; r++) O[t][r] = 0.f;
    float m0 = -1e30f, m1 = -1e30f, l0 = 0.f, l1 = 0.f;

    const float sc = 0.08838834764831845f;
    const int row0 = q0 + w * 16 + g;
    const int row1 = row0 + 8;

#define KV_ISSUE(kt_)                                                         \
    do {                                                                      \
        const int kk0 = (kt_) * 64;                                           \
        const uint32_t kb_ = ukv + ((kt_) & 1) * (2 * KVB);                   \
        _Pragma("unroll")                                                     \
        for (int t = 0; t < 4; t++) {                                         \
            int idx = tid + t * 256;                                          \
            int r = idx >> 4;                                                 \
            int dd = (idx & 15) * 8;                                          \
            uint32_t soff = (r * STQ + dd) * 2;                               \
            size_t ga = (size_t)(kk0 + r) * HD_ + dd;                         \
            CP_ASYNC16(kb_ + soff,       Kf + ga);                            \
            CP_ASYNC16(kb_ + KVB + soff, Vf + ga);                            \
        }                                                                     \
        CP_COMMIT();                                                          \
    } while (0)

    KV_ISSUE(0);

    const int ktn = (q0 + 128) >> 6;
#pragma unroll 1
    for (int kt = 0; kt < ktn; kt++) {
        const int k0 = kt * 64;
        CP_WAIT0();
        __syncthreads();
        if (kt + 1 < ktn) KV_ISSUE(kt + 1);

        const uint32_t uKf = ukv + (kt & 1) * (2 * KVB);
        const uint32_t uVf = uKf + KVB;

        const bool active = (k0 <= q0 + w * 16 + 15);
        if (active) {
            float S[8][4];
#pragma unroll
            for (int t = 0; t < 8; t++)
#pragma unroll
                for (int r = 0; r < 4; r++) S[t][r] = 0.f;

#pragma unroll
            for (int kc = 0; kc < 8; kc++) {
                const int col = kc * 16 + fcol;
                uint32_t qh[4], ql[4];
                uint32_t qoff = ((w * 16 + frow) * STQ + col) * 2;
                LDSM_X4(qh, uQh + qoff);
                LDSM_X4(ql, uQl + qoff);
#pragma unroll
                for (int p = 0; p < 4; p++) {
                    uint32_t koff = ((p * 16 + frow) * STQ + col) * 2;
                    uint32_t kf[4];
                    LDSM_X4(kf, uKf + koff);
                    uint32_t b0[2] = {kf[0], kf[2]};
                    uint32_t b1[2] = {kf[1], kf[3]};
                    MMA_F16(S[2 * p], qh, b0);
                    MMA_F16(S[2 * p + 1], qh, b1);
                    MMA_F16(S[2 * p], ql, b0);
                    MMA_F16(S[2 * p + 1], ql, b1);
                }
            }

            const bool maskneed = (k0 + 63 > row0);
#pragma unroll
            for (int t = 0; t < 8; t++) {
                int c0 = k0 + 8 * t + 2 * qp;
#pragma unroll
                for (int r = 0; r < 4; r++) {
                    S[t][r] *= sc;
                    if (maskneed) {
                        int colg = c0 + (r & 1);
                        int rowg = (r < 2) ? row0 : row1;
                        if (colg > rowg) S[t][r] = -1e9f;
                    }
                }
            }

            float rm0 = -1e30f, rm1 = -1e30f;
#pragma unroll
            for (int t = 0; t < 8; t++) {
                rm0 = fmaxf(rm0, fmaxf(S[t][0], S[t][1]));
                rm1 = fmaxf(rm1, fmaxf(S[t][2], S[t][3]));
            }
            rm0 = fmaxf(rm0, __shfl_xor_sync(0xffffffffu, rm0, 1));
            rm0 = fmaxf(rm0, __shfl_xor_sync(0xffffffffu, rm0, 2));
            rm1 = fmaxf(rm1, __shfl_xor_sync(0xffffffffu, rm1, 1));
            rm1 = fmaxf(rm1, __shfl_xor_sync(0xffffffffu, rm1, 2));
            float mn0 = fmaxf(m0, rm0), mn1 = fmaxf(m1, rm1);
            float a0 = __expf(m0 - mn0), a1 = __expf(m1 - mn1);
            float rs0 = 0.f, rs1 = 0.f;
#pragma unroll
            for (int t = 0; t < 8; t++) {
                S[t][0] = __expf(S[t][0] - mn0);
                S[t][1] = __expf(S[t][1] - mn0);
                S[t][2] = __expf(S[t][2] - mn1);
                S[t][3] = __expf(S[t][3] - mn1);
                rs0 += S[t][0] + S[t][1];
                rs1 += S[t][2] + S[t][3];
            }
            rs0 += __shfl_xor_sync(0xffffffffu, rs0, 1);
            rs0 += __shfl_xor_sync(0xffffffffu, rs0, 2);
            rs1 += __shfl_xor_sync(0xffffffffu, rs1, 1);
            rs1 += __shfl_xor_sync(0xffffffffu, rs1, 2);
            l0 = l0 * a0 + rs0;
            l1 = l1 * a1 + rs1;
            m0 = mn0;
            m1 = mn1;
#pragma unroll
            for (int t = 0; t < 16; t++) {
                O[t][0] *= a0; O[t][1] *= a0;
                O[t][2] *= a1; O[t][3] *= a1;
            }

            uint32_t ph[4][4], pl[4][4];
#pragma unroll
            for (int kc2 = 0; kc2 < 4; kc2++) {
                int t0 = 2 * kc2, t1 = 2 * kc2 + 1;
                float src[8] = {S[t0][0], S[t0][1], S[t0][2], S[t0][3],
                                S[t1][0], S[t1][1], S[t1][2], S[t1][3]};
                float hv[8], lv[8];
#pragma unroll
                for (int e = 0; e < 8; e++) {
                    hv[e] = __half2float(__float2half_rn(src[e]));
                    lv[e] = src[e] - hv[e];
                }
                ph[kc2][0] = packh(hv[0], hv[1]);
                ph[kc2][1] = packh(hv[2], hv[3]);
                ph[kc2][2] = packh(hv[4], hv[5]);
                ph[kc2][3] = packh(hv[6], hv[7]);
                pl[kc2][0] = packh(lv[0], lv[1]);
                pl[kc2][1] = packh(lv[2], lv[3]);
                pl[kc2][2] = packh(lv[4], lv[5]);
                pl[kc2][3] = packh(lv[6], lv[7]);
            }

#pragma unroll
            for (int kc2 = 0; kc2 < 4; kc2++) {
#pragma unroll
                for (int p = 0; p < 8; p++) {
                    uint32_t voff = ((kc2 * 16 + frow) * STQ + p * 16 + fcol) * 2;
                    uint32_t vf[4];
                    LDSM_X4T(vf, uVf + voff);
                    uint32_t b0[2] = {vf[0], vf[1]};
                    uint32_t b1[2] = {vf[2], vf[3]};
                    MMA_F16(O[2 * p], ph[kc2], b0);
                    MMA_F16(O[2 * p + 1], ph[kc2], b1);
                    MMA_F16(O[2 * p], pl[kc2], b0);
                    MMA_F16(O[2 * p + 1], pl[kc2], b1);
                }
            }
        }
    }
#undef KV_ISSUE

    // ---- normalize + write pre-split ctx [b][s][h][d] ----
    float inv0 = 1.f / l0, inv1 = 1.f / l1;
    size_t base0 = (((size_t)b * S_ + row0) * NH_ + h) * HD_;
    size_t base1 = (((size_t)b * S_ + row1) * NH_ + h) * HD_;
#pragma unroll
    for (int t = 0; t < 16; t++) {
        int d = 8 * t + 2 * qp;
        float o0 = O[t][0] * inv0, o1 = O[t][1] * inv0;
        float o2 = O[t][2] * inv1, o3 = O[t][3] * inv1;
        float h0 = __half2float(__float2half_rn(o0));
        float h1 = __half2float(__float2half_rn(o1));
        float h2 = __half2float(__float2half_rn(o2));
        float h3 = __half2float(__float2half_rn(o3));
        *(uint32_t*)&g_ctxh[base0 + d] = packh(h0, h1);
        *(uint32_t*)&g_ctxl[base0 + d] = packh(o0 - h0, o1 - h1);
        *(uint32_t*)&g_ctxh[base1 + d] = packh(h2, h3);
        *(uint32_t*)&g_ctxl[base1 + d] = packh(o2 - h2, o3 - h3);
    }
}

// ---------------------------------------------------------------------------
extern "C" void kernel_launch(void* const* d_in, const int* in_sizes, int n_in,
                              void* d_out, int out_size) {
    (void)in_sizes; (void)n_in; (void)out_size;
    const float* x     = (const float*)d_in[0];
    const float* w_qkv = (const float*)d_in[1];
    const float* w_o   = (const float*)d_in[2];
    const float* cosT  = (const float*)d_in[3];
    const float* sinT  = (const float*)d_in[4];
    float* out = (float*)d_out;

    cudaFuncSetAttribute(attn_mma_kernel, cudaFuncAttributeMaxDynamicSharedMemorySize, ATTN_SMEM);
    cudaFuncSetAttribute((const void*)gemm_f16_kernel<0, 2>, cudaFuncAttributeMaxDynamicSharedMemorySize, GSMEM);
    cudaFuncSetAttribute((const void*)gemm_f16_kernel<0, 1>, cudaFuncAttributeMaxDynamicSharedMemorySize, GSMEM);
    cudaFuncSetAttribute((const void*)gemm_f16_kernel<1, 2>, cudaFuncAttributeMaxDynamicSharedMemorySize, GSMEM);

    h16 *xh, *xl, *wqf, *wof, *ctxh, *ctxl;
    cudaGetSymbolAddress((void**)&xh, g_xh);
    cudaGetSymbolAddress((void**)&xl, g_xl);
    cudaGetSymbolAddress((void**)&wqf, g_wqf);
    cudaGetSymbolAddress((void**)&wof, g_wof);
    cudaGetSymbolAddress((void**)&ctxh, g_ctxh);
    cudaGetSymbolAddress((void**)&ctxl, g_ctxl);

    int n4x = (B_ * S_ * HID_) / 4;
    int n4q = (3 * HID_ * HID_) / 4;
    int n4o = (HID_ * HID_) / 4;

    split_kernel<<<(n4x + 255) / 256, 256>>>(x, xh, xl, n4x);
    conv_kernel<<<(n4q + 255) / 256, 256>>>(w_qkv, wqf, n4q);
    conv_kernel<<<(n4o + 255) / 256, 256>>>(w_o, wof, n4o);

    // 1a) Q projection (2-pass, N = [0, 2048))
    gemm_f16_kernel<0, 2><<<dim3(2048 / 128, 4096 / 128), 256, GSMEM>>>(
        xh, xl, wqf, nullptr, 0);
    // 1b) K,V projection (1-pass, N = [2048, 6144)) — outputs get rounded to
    //     fp16 by rope_conv anyway; single-pass error is within budget.
    gemm_f16_kernel<0, 1><<<dim3(4096 / 128, 4096 / 128), 256, GSMEM>>>(
        xh, xl, wqf + (size_t)2048 * KDIM, nullptr, 2048);

    // 2) RoPE + convert
    rope_conv_kernel<<<(3 * BNHS * 64) / 256, 256>>>(cosT, sinT);

    // 3) Flash attention
    attn_mma_kernel<<<dim3(S_ / 128, B_ * NH_), 256, ATTN_SMEM>>>();

    // 4) Output projection (2-pass)
    gemm_f16_kernel<1, 2><<<dim3(2048 / 128, 4096 / 128), 256, GSMEM>>>(
        ctxh, ctxl, wof, out, 0);
}

// round 17
// speedup vs baseline: 1.6043x; 1.2464x over previous
#include <cuda_runtime.h>
#include <cuda_fp16.h>
#include <cstdint>
#include <math.h>

#define B_   2
#define S_   2048
#define HID_ 2048
#define NH_  16
#define HD_  128
#define KDIM 2048
#define BNHS (B_ * NH_ * S_)

typedef __half h16;

// ---- persistent buffers ----
__device__ float g_qkv[(size_t)3 * BNHS * HD_];   // [which][b][h][s][d] fp32
__device__ h16 g_xh[(size_t)B_ * S_ * HID_];
__device__ h16 g_xl[(size_t)B_ * S_ * HID_];
__device__ h16 g_wqf[(size_t)3 * HID_ * HID_];
__device__ h16 g_wof[(size_t)HID_ * HID_];
__device__ h16 g_qf[(size_t)BNHS * HD_];
__device__ h16 g_kf[(size_t)BNHS * HD_];
__device__ h16 g_vf[(size_t)BNHS * HD_];
__device__ h16 g_ctxf[(size_t)B_ * S_ * HID_];    // [b][s][h][d] single fp16

// ---------------- helpers ----------------
__device__ __forceinline__ uint32_t s2u(const void* p) {
    return (uint32_t)__cvta_generic_to_shared(p);
}
__device__ __forceinline__ uint32_t packh(float lo, float hi) {
    uint32_t r;
    asm("cvt.rn.f16x2.f32 %0, %1, %2;" : "=r"(r) : "f"(hi), "f"(lo));
    return r;
}

#define MMA_F16(d, a, b)                                                      \
    asm volatile(                                                             \
        "mma.sync.aligned.m16n8k16.row.col.f32.f16.f16.f32 "                  \
        "{%0,%1,%2,%3}, {%4,%5,%6,%7}, {%8,%9}, {%0,%1,%2,%3};\n"             \
        : "+f"((d)[0]), "+f"((d)[1]), "+f"((d)[2]), "+f"((d)[3])              \
        : "r"((a)[0]), "r"((a)[1]), "r"((a)[2]), "r"((a)[3]),                 \
          "r"((b)[0]), "r"((b)[1]))

#define LDSM_X4(r, addr)                                                      \
    asm volatile("ldmatrix.sync.aligned.m8n8.x4.shared.b16 {%0,%1,%2,%3}, [%4];" \
                 : "=r"((r)[0]), "=r"((r)[1]), "=r"((r)[2]), "=r"((r)[3])     \
                 : "r"(addr))

#define LDSM_X4T(r, addr)                                                     \
    asm volatile("ldmatrix.sync.aligned.m8n8.x4.trans.shared.b16 {%0,%1,%2,%3}, [%4];" \
                 : "=r"((r)[0]), "=r"((r)[1]), "=r"((r)[2]), "=r"((r)[3])     \
                 : "r"(addr))

#define CP_ASYNC16(dst, src)                                                  \
    asm volatile("cp.async.cg.shared.global [%0], [%1], 16;" ::               \
                 "r"(dst), "l"(src))
#define CP_COMMIT() asm volatile("cp.async.commit_group;" ::: "memory")
#define CP_WAIT1()  asm volatile("cp.async.wait_group 1;" ::: "memory")
#define CP_WAIT0()  asm volatile("cp.async.wait_group 0;" ::: "memory")

// ---------------------------------------------------------------------------
// Prep: split fp32 -> fp16 hi/lo, and plain fp32 -> fp16 convert.
// ---------------------------------------------------------------------------
__global__ __launch_bounds__(256)
void split_kernel(const float* __restrict__ src, h16* __restrict__ h,
                  h16* __restrict__ l, int n4) {
    int i = blockIdx.x * 256 + threadIdx.x;
    if (i >= n4) return;
    float4 v = *(const float4*)&src[(size_t)i * 4];
    float f[4] = {v.x, v.y, v.z, v.w};
    float hf[4], lf[4];
#pragma unroll
    for (int e = 0; e < 4; e++) {
        hf[e] = __half2float(__float2half_rn(f[e]));
        lf[e] = f[e] - hf[e];
    }
    *(uint2*)&h[(size_t)i * 4] = make_uint2(packh(hf[0], hf[1]), packh(hf[2], hf[3]));
    *(uint2*)&l[(size_t)i * 4] = make_uint2(packh(lf[0], lf[1]), packh(lf[2], lf[3]));
}

__global__ __launch_bounds__(256)
void conv_kernel(const float* __restrict__ src, h16* __restrict__ dst, int n4) {
    int i = blockIdx.x * 256 + threadIdx.x;
    if (i >= n4) return;
    float4 v = *(const float4*)&src[(size_t)i * 4];
    *(uint2*)&dst[(size_t)i * 4] = make_uint2(packh(v.x, v.y), packh(v.z, v.w));
}

// ---------------------------------------------------------------------------
// fp16 GEMM: BM=BN=128, BK=32/stage, 3-stage cp.async, 1 barrier/stage,
// 256 thr, 8 warps (4Mx2N), warp tile 32x64.
// PASSES=2: A = Ah + Al. PASSES=1: A = Ah only.
// MODE 0: scatter fp32 q/k/v into g_qkv (gn offset nbase). MODE 1: fp32 out.
// ---------------------------------------------------------------------------
#define GST 40
#define ARRB (128 * GST * 2)
#define STGB (3 * ARRB)
#define GSMEM (3 * STGB)

template <int MODE, int PASSES>
__global__ __launch_bounds__(256, 2)
void gemm_f16_kernel(const h16* __restrict__ Agh, const h16* __restrict__ Agl,
                     const h16* __restrict__ Bgf, float* __restrict__ Cout,
                     int nbase) {
    extern __shared__ char smem[];
    const uint32_t sbase = s2u(smem);
    const int m0 = blockIdx.y * 128;
    const int n0 = blockIdx.x * 128;
    const int tid = threadIdx.x;
    const int lane = tid & 31;
    const int warp = tid >> 5;
    const int warpM = warp & 3;
    const int warpN = warp >> 2;

    const int g = lane >> 2;
    const int qp = lane & 3;
    const int frow = lane & 15;
    const int fcol = (lane >> 4) << 3;

    float C[2][8][4];
#pragma unroll
    for (int mt = 0; mt < 2; mt++)
#pragma unroll
        for (int nt = 0; nt < 8; nt++)
#pragma unroll
            for (int r = 0; r < 4; r++) C[mt][nt][r] = 0.f;

#define ISSUE(s)                                                              \
    do {                                                                      \
        const int k0_ = (s) * 32;                                             \
        const uint32_t sb_ = sbase + ((s) % 3) * STGB;                        \
        _Pragma("unroll")                                                     \
        for (int t = 0; t < 2; t++) {                                         \
            int idx = tid + t * 256;                                          \
            int row = idx >> 2;                                               \
            int qtr = (idx & 3) * 8;                                          \
            uint32_t soff = (row * GST + qtr) * 2;                            \
            size_t ga = (size_t)(m0 + row) * KDIM + k0_ + qtr;                \
            size_t gb = (size_t)(n0 + row) * KDIM + k0_ + qtr;                \
            CP_ASYNC16(sb_ + soff, Agh + ga);                                 \
            if (PASSES == 2) CP_ASYNC16(sb_ + ARRB + soff, Agl + ga);         \
            CP_ASYNC16(sb_ + 2 * ARRB + soff, Bgf + gb);                      \
        }                                                                     \
        CP_COMMIT();                                                          \
    } while (0)

    ISSUE(0);
    ISSUE(1);

    const int NST = KDIM / 32;
#pragma unroll 1
    for (int s = 0; s < NST; s++) {
        if (s == NST - 1) CP_WAIT0(); else CP_WAIT1();
        __syncthreads();
        if (s + 2 < NST) ISSUE(s + 2);

        const uint32_t uAh = sbase + (s % 3) * STGB;
        const uint32_t uAl = uAh + ARRB;
        const uint32_t uBf = uAh + 2 * ARRB;

#pragma unroll
        for (int kc = 0; kc < 2; kc++) {
            const int col = kc * 16 + fcol;
            uint32_t a_hi[2][4], a_lo[2][4];
#pragma unroll
            for (int mt = 0; mt < 2; mt++) {
                uint32_t off = ((warpM * 32 + mt * 16 + frow) * GST + col) * 2;
                LDSM_X4(a_hi[mt], uAh + off);
                if (PASSES == 2) LDSM_X4(a_lo[mt], uAl + off);
            }
#pragma unroll
            for (int p = 0; p < 4; p++) {
                uint32_t off = ((warpN * 64 + p * 16 + frow) * GST + col) * 2;
                uint32_t kb[4];
                LDSM_X4(kb, uBf + off);
                uint32_t b0[2] = {kb[0], kb[2]};
                uint32_t b1[2] = {kb[1], kb[3]};
#pragma unroll
                for (int mt = 0; mt < 2; mt++) {
                    MMA_F16(C[mt][2 * p], a_hi[mt], b0);
                    MMA_F16(C[mt][2 * p + 1], a_hi[mt], b1);
                    if (PASSES == 2) {
                        MMA_F16(C[mt][2 * p], a_lo[mt], b0);
                        MMA_F16(C[mt][2 * p + 1], a_lo[mt], b1);
                    }
                }
            }
        }
    }
#undef ISSUE

    // ---- epilogue ----
#pragma unroll
    for (int mt = 0; mt < 2; mt++) {
#pragma unroll
        for (int nt = 0; nt < 8; nt++) {
            int gm0 = m0 + warpM * 32 + mt * 16 + g;
            int gn = nbase + n0 + warpN * 64 + nt * 8 + qp * 2;
            float2 v0 = make_float2(C[mt][nt][0], C[mt][nt][1]);
            float2 v1 = make_float2(C[mt][nt][2], C[mt][nt][3]);
            if (MODE == 0) {
                int which = gn >> 11;
                int rem = gn & 2047;
                int h = rem >> 7;
                int d = rem & 127;
#pragma unroll
                for (int rr = 0; rr < 2; rr++) {
                    int gm = gm0 + rr * 8;
                    int b = gm >> 11;
                    int s = gm & 2047;
                    size_t off = (size_t)which * ((size_t)BNHS * HD_) +
                                 (((size_t)(b * NH_ + h)) * S_ + s) * HD_ + d;
                    *(float2*)&g_qkv[off] = rr ? v1 : v0;
                }
            } else {
                *(float2*)&Cout[(size_t)gm0 * HID_ + gn] = v0;
                *(float2*)&Cout[(size_t)(gm0 + 8) * HID_ + gn] = v1;
            }
        }
    }
}

// ---------------------------------------------------------------------------
// RoPE + convert: Q -> qf fp16; K -> kf fp16; V -> vf fp16 (all single).
// ---------------------------------------------------------------------------
__global__ __launch_bounds__(256)
void rope_conv_kernel(const float* __restrict__ cosT, const float* __restrict__ sinT) {
    long long t = (long long)blockIdx.x * 256 + threadIdx.x;
    int d = (int)(t & 63);
    long long row = t >> 6;
    int which = (int)(row / BNHS);
    long long lr = row % BNHS;
    int s = (int)(lr % S_);
    const float* p = g_qkv + row * HD_;
    float x1 = p[d];
    float x2 = p[d + 64];

    if (which < 2) {
        float c1 = cosT[s * HD_ + d];
        float s1 = sinT[s * HD_ + d];
        float c2 = cosT[s * HD_ + d + 64];
        float s2 = sinT[s * HD_ + d + 64];
        float r1 = x1 * c1 - x2 * s1;
        float r2 = x2 * c2 + x1 * s2;
        h16* dst = (which == 0) ? g_qf : g_kf;
        dst[lr * HD_ + d] = __float2half_rn(r1);
        dst[lr * HD_ + d + 64] = __float2half_rn(r2);
    } else {
        g_vf[lr * HD_ + d] = __float2half_rn(x1);
        g_vf[lr * HD_ + d + 64] = __float2half_rn(x2);
    }
}

// ---------------------------------------------------------------------------
// Single-pass fp16 causal flash attention (fp32 accum), cp.async K/V double
// buffer. BQ=128, BK=64, 256 threads. Writes ctx as single fp16.
// ---------------------------------------------------------------------------
#define STQ 136
#define KVB (64 * STQ * 2)
#define ATTN_SMEM (128 * STQ * 2 + 4 * KVB)

__global__ __launch_bounds__(256, 1)
void attn_mma_kernel() {
    extern __shared__ char smraw[];
    h16* sQ = (h16*)smraw;
    char* kvbase = (char*)(sQ + 128 * STQ);
    const uint32_t ukv = s2u(kvbase);

    const int tid = threadIdx.x;
    const int lane = tid & 31;
    const int w = tid >> 5;
    const int qp = lane & 3;
    const int g = lane >> 2;
    const int frow = lane & 15;
    const int fcol = (lane >> 4) << 3;

    const int qt = blockIdx.x;
    const int bh = blockIdx.y;
    const int b = bh >> 4;
    const int h = bh & 15;
    const int q0 = qt * 128;

    const size_t hs = (size_t)S_ * HD_;
    const h16* Qf = g_qf + (size_t)bh * hs;
    const h16* Kf = g_kf + (size_t)bh * hs;
    const h16* Vf = g_vf + (size_t)bh * hs;

    // ---- load Q tile (128 x 128) fp16 ----
#pragma unroll
    for (int i = 0; i < 4; i++) {
        int idx = tid + i * 256;
        int r = idx >> 3;
        int dd = (idx & 7) * 16;
        size_t ga = (size_t)(q0 + r) * HD_ + dd;
        *(uint4*)&sQ[r * STQ + dd] = *(const uint4*)&Qf[ga];
        *(uint4*)&sQ[r * STQ + dd + 8] = *(const uint4*)&Qf[ga + 8];
    }

    const uint32_t uQ = s2u(sQ);

    float O[16][4];
#pragma unroll
    for (int t = 0; t < 16; t++)
#pragma unroll
        for (int r = 0; r < 4; r++) O[t][r] = 0.f;
    float m0 = -1e30f, m1 = -1e30f, l0 = 0.f, l1 = 0.f;

    const float sc = 0.08838834764831845f;
    const int row0 = q0 + w * 16 + g;
    const int row1 = row0 + 8;

#define KV_ISSUE(kt_)                                                         \
    do {                                                                      \
        const int kk0 = (kt_) * 64;                                           \
        const uint32_t kb_ = ukv + ((kt_) & 1) * (2 * KVB);                   \
        _Pragma("unroll")                                                     \
        for (int t = 0; t < 4; t++) {                                         \
            int idx = tid + t * 256;                                          \
            int r = idx >> 4;                                                 \
            int dd = (idx & 15) * 8;                                          \
            uint32_t soff = (r * STQ + dd) * 2;                               \
            size_t ga = (size_t)(kk0 + r) * HD_ + dd;                         \
            CP_ASYNC16(kb_ + soff,       Kf + ga);                            \
            CP_ASYNC16(kb_ + KVB + soff, Vf + ga);                            \
        }                                                                     \
        CP_COMMIT();                                                          \
    } while (0)

    KV_ISSUE(0);

    const int ktn = (q0 + 128) >> 6;
#pragma unroll 1
    for (int kt = 0; kt < ktn; kt++) {
        const int k0 = kt * 64;
        CP_WAIT0();
        __syncthreads();
        if (kt + 1 < ktn) KV_ISSUE(kt + 1);

        const uint32_t uKf = ukv + (kt & 1) * (2 * KVB);
        const uint32_t uVf = uKf + KVB;

        const bool active = (k0 <= q0 + w * 16 + 15);
        if (active) {
            float S[8][4];
#pragma unroll
            for (int t = 0; t < 8; t++)
#pragma unroll
                for (int r = 0; r < 4; r++) S[t][r] = 0.f;

#pragma unroll
            for (int kc = 0; kc < 8; kc++) {
                const int col = kc * 16 + fcol;
                uint32_t qa[4];
                uint32_t qoff = ((w * 16 + frow) * STQ + col) * 2;
                LDSM_X4(qa, uQ + qoff);
#pragma unroll
                for (int p = 0; p < 4; p++) {
                    uint32_t koff = ((p * 16 + frow) * STQ + col) * 2;
                    uint32_t kf[4];
                    LDSM_X4(kf, uKf + koff);
                    uint32_t b0[2] = {kf[0], kf[2]};
                    uint32_t b1[2] = {kf[1], kf[3]};
                    MMA_F16(S[2 * p], qa, b0);
                    MMA_F16(S[2 * p + 1], qa, b1);
                }
            }

            const bool maskneed = (k0 + 63 > row0);
#pragma unroll
            for (int t = 0; t < 8; t++) {
                int c0 = k0 + 8 * t + 2 * qp;
#pragma unroll
                for (int r = 0; r < 4; r++) {
                    S[t][r] *= sc;
                    if (maskneed) {
                        int colg = c0 + (r & 1);
                        int rowg = (r < 2) ? row0 : row1;
                        if (colg > rowg) S[t][r] = -1e9f;
                    }
                }
            }

            float rm0 = -1e30f, rm1 = -1e30f;
#pragma unroll
            for (int t = 0; t < 8; t++) {
                rm0 = fmaxf(rm0, fmaxf(S[t][0], S[t][1]));
                rm1 = fmaxf(rm1, fmaxf(S[t][2], S[t][3]));
            }
            rm0 = fmaxf(rm0, __shfl_xor_sync(0xffffffffu, rm0, 1));
            rm0 = fmaxf(rm0, __shfl_xor_sync(0xffffffffu, rm0, 2));
            rm1 = fmaxf(rm1, __shfl_xor_sync(0xffffffffu, rm1, 1));
            rm1 = fmaxf(rm1, __shfl_xor_sync(0xffffffffu, rm1, 2));
            float mn0 = fmaxf(m0, rm0), mn1 = fmaxf(m1, rm1);
            float a0 = __expf(m0 - mn0), a1 = __expf(m1 - mn1);
            float rs0 = 0.f, rs1 = 0.f;
#pragma unroll
            for (int t = 0; t < 8; t++) {
                S[t][0] = __expf(S[t][0] - mn0);
                S[t][1] = __expf(S[t][1] - mn0);
                S[t][2] = __expf(S[t][2] - mn1);
                S[t][3] = __expf(S[t][3] - mn1);
                rs0 += S[t][0] + S[t][1];
                rs1 += S[t][2] + S[t][3];
            }
            rs0 += __shfl_xor_sync(0xffffffffu, rs0, 1);
            rs0 += __shfl_xor_sync(0xffffffffu, rs0, 2);
            rs1 += __shfl_xor_sync(0xffffffffu, rs1, 1);
            rs1 += __shfl_xor_sync(0xffffffffu, rs1, 2);
            l0 = l0 * a0 + rs0;
            l1 = l1 * a1 + rs1;
            m0 = mn0;
            m1 = mn1;
#pragma unroll
            for (int t = 0; t < 16; t++) {
                O[t][0] *= a0; O[t][1] *= a0;
                O[t][2] *= a1; O[t][3] *= a1;
            }

            // P fragments (single fp16)
            uint32_t ph[4][4];
#pragma unroll
            for (int kc2 = 0; kc2 < 4; kc2++) {
                int t0 = 2 * kc2, t1 = 2 * kc2 + 1;
                ph[kc2][0] = packh(S[t0][0], S[t0][1]);
                ph[kc2][1] = packh(S[t0][2], S[t0][3]);
                ph[kc2][2] = packh(S[t1][0], S[t1][1]);
                ph[kc2][3] = packh(S[t1][2], S[t1][3]);
            }

#pragma unroll
            for (int kc2 = 0; kc2 < 4; kc2++) {
#pragma unroll
                for (int p = 0; p < 8; p++) {
                    uint32_t voff = ((kc2 * 16 + frow) * STQ + p * 16 + fcol) * 2;
                    uint32_t vf[4];
                    LDSM_X4T(vf, uVf + voff);
                    uint32_t b0[2] = {vf[0], vf[1]};
                    uint32_t b1[2] = {vf[2], vf[3]};
                    MMA_F16(O[2 * p], ph[kc2], b0);
                    MMA_F16(O[2 * p + 1], ph[kc2], b1);
                }
            }
        }
    }
#undef KV_ISSUE

    // ---- normalize + write single-fp16 ctx [b][s][h][d] ----
    float inv0 = 1.f / l0, inv1 = 1.f / l1;
    size_t base0 = (((size_t)b * S_ + row0) * NH_ + h) * HD_;
    size_t base1 = (((size_t)b * S_ + row1) * NH_ + h) * HD_;
#pragma unroll
    for (int t = 0; t < 16; t++) {
        int d = 8 * t + 2 * qp;
        *(uint32_t*)&g_ctxf[base0 + d] = packh(O[t][0] * inv0, O[t][1] * inv0);
        *(uint32_t*)&g_ctxf[base1 + d] = packh(O[t][2] * inv1, O[t][3] * inv1);
    }
}

// ---------------------------------------------------------------------------
extern "C" void kernel_launch(void* const* d_in, const int* in_sizes, int n_in,
                              void* d_out, int out_size) {
    (void)in_sizes; (void)n_in; (void)out_size;
    const float* x     = (const float*)d_in[0];
    const float* w_qkv = (const float*)d_in[1];
    const float* w_o   = (const float*)d_in[2];
    const float* cosT  = (const float*)d_in[3];
    const float* sinT  = (const float*)d_in[4];
    float* out = (float*)d_out;

    cudaFuncSetAttribute(attn_mma_kernel, cudaFuncAttributeMaxDynamicSharedMemorySize, ATTN_SMEM);
    cudaFuncSetAttribute((const void*)gemm_f16_kernel<0, 2>, cudaFuncAttributeMaxDynamicSharedMemorySize, GSMEM);
    cudaFuncSetAttribute((const void*)gemm_f16_kernel<0, 1>, cudaFuncAttributeMaxDynamicSharedMemorySize, GSMEM);
    cudaFuncSetAttribute((const void*)gemm_f16_kernel<1, 1>, cudaFuncAttributeMaxDynamicSharedMemorySize, GSMEM);

    h16 *xh, *xl, *wqf, *wof, *ctxf;
    cudaGetSymbolAddress((void**)&xh, g_xh);
    cudaGetSymbolAddress((void**)&xl, g_xl);
    cudaGetSymbolAddress((void**)&wqf, g_wqf);
    cudaGetSymbolAddress((void**)&wof, g_wof);
    cudaGetSymbolAddress((void**)&ctxf, g_ctxf);

    int n4x = (B_ * S_ * HID_) / 4;
    int n4q = (3 * HID_ * HID_) / 4;
    int n4o = (HID_ * HID_) / 4;

    split_kernel<<<(n4x + 255) / 256, 256>>>(x, xh, xl, n4x);
    conv_kernel<<<(n4q + 255) / 256, 256>>>(w_qkv, wqf, n4q);
    conv_kernel<<<(n4o + 255) / 256, 256>>>(w_o, wof, n4o);

    // 1a) Q projection (2-pass — softmax logits are precision-sensitive)
    gemm_f16_kernel<0, 2><<<dim3(2048 / 128, 4096 / 128), 256, GSMEM>>>(
        xh, xl, wqf, nullptr, 0);
    // 1b) K,V projection (1-pass — rounded to fp16 immediately anyway)
    gemm_f16_kernel<0, 1><<<dim3(4096 / 128, 4096 / 128), 256, GSMEM>>>(
        xh, xl, wqf + (size_t)2048 * KDIM, nullptr, 2048);

    // 2) RoPE + convert to fp16
    rope_conv_kernel<<<(3 * BNHS * 64) / 256, 256>>>(cosT, sinT);

    // 3) Flash attention (single-pass fp16, fp32 accum)
    attn_mma_kernel<<<dim3(S_ / 128, B_ * NH_), 256, ATTN_SMEM>>>();

    // 4) Output projection (1-pass: ctx single fp16)
    gemm_f16_kernel<1, 1><<<dim3(2048 / 128, 4096 / 128), 256, GSMEM>>>(
        ctxf, nullptr, wof, out, 0);
}